// round 3
// baseline (speedup 1.0000x reference)
#include <cuda_runtime.h>
#include <mma.h>
#include <math.h>

using namespace nvcuda;

#define BATCH   4
#define SEQ     1024
#define DMODEL  256
#define NHEAD   8
#define DHEAD   32
#define DFF     1024
#define NLAYER  6
#define TOK     (BATCH*SEQ)

__device__ __align__(16) float g_scratch[6*TOK*DMODEL + TOK*DFF];
#define OFF_X 0
#define OFF_T (1*TOK*DMODEL)
#define OFF_Q (2*TOK*DMODEL)
#define OFF_K (3*TOK*DMODEL)
#define OFF_V (4*TOK*DMODEL)
#define OFF_C (5*TOK*DMODEL)
#define OFF_H (6*TOK*DMODEL)

// ---------------- cp.async helpers ----------------
__device__ __forceinline__ void cpa16(float* dst, const float* src) {
    unsigned s = (unsigned)__cvta_generic_to_shared(dst);
    asm volatile("cp.async.cg.shared.global [%0], [%1], 16;\n" :: "r"(s), "l"(src));
}
__device__ __forceinline__ void cpa_commit() {
    asm volatile("cp.async.commit_group;\n");
}
template<int N>
__device__ __forceinline__ void cpa_wait() {
    asm volatile("cp.async.wait_group %0;\n" :: "n"(N));
}

// ---------------- positional embedding value ----------------
__device__ __forceinline__ float pe_val(int l, int d) {
    int j = d & 127;
    double e = -(2.0*(double)j/256.0) * 9.210340371976184;  // ln(10000)
    float invf = (float)exp(e);
    float arg = (float)l * invf;
    return (d < 128) ? sinf(arg) : cosf(arg);
}

// ---------------- embed (+PE layer 0) ----------------
__global__ void embed_kernel(const float* __restrict__ dec,
                             const float* __restrict__ W,
                             const float* __restrict__ b,
                             float* __restrict__ x) {
    int row = blockIdx.x;
    int d   = threadIdx.x;
    const float* in = dec + row*3;
    float acc = b[d] + in[0]*W[d] + in[1]*W[DMODEL+d] + in[2]*W[2*DMODEL+d];
    x[row*DMODEL + d] = acc + pe_val(row & (SEQ-1), d);
}

// ---------------- LayerNorm (optional t2 addend for split-K, optional +PE) -------
__global__ void ln_kernel(const float* __restrict__ t,
                          const float* __restrict__ t2,
                          const float* __restrict__ g,
                          const float* __restrict__ b,
                          float* __restrict__ out, int addpe) {
    int row = blockIdx.x;
    int d   = threadIdx.x;
    float v = t[row*DMODEL + d];
    if (t2) v += t2[row*DMODEL + d];

    __shared__ float red[8];
    __shared__ float stats[2];

    float s = v;
    #pragma unroll
    for (int o = 16; o; o >>= 1) s += __shfl_xor_sync(0xffffffffu, s, o);
    if ((d & 31) == 0) red[d >> 5] = s;
    __syncthreads();
    if (d == 0) {
        float m = 0.f;
        #pragma unroll
        for (int i = 0; i < 8; i++) m += red[i];
        stats[0] = m * (1.0f/DMODEL);
    }
    __syncthreads();
    float mean = stats[0];
    float dv = v - mean;
    float s2 = dv*dv;
    #pragma unroll
    for (int o = 16; o; o >>= 1) s2 += __shfl_xor_sync(0xffffffffu, s2, o);
    if ((d & 31) == 0) red[d >> 5] = s2;
    __syncthreads();
    if (d == 0) {
        float var = 0.f;
        #pragma unroll
        for (int i = 0; i < 8; i++) var += red[i];
        stats[1] = rsqrtf(var * (1.0f/DMODEL) + 1e-5f);
    }
    __syncthreads();
    float o = dv * stats[1] * g[d] + b[d];
    if (addpe) o += pe_val(row & (SEQ-1), d);
    out[row*DMODEL + d] = o;
}

// ---------------- tf32 GEMM: 64x64x32, 256 thr, 3-stage cp.async, split-K ----------
// grid.x = nsel*(N/64), grid.y = M/64, grid.z = ksplit
// K param = K per z-slice; A leading dim = K*gridDim.z.
struct GArgs {
    const float* A[3];
    const float* W[3];
    const float* bi[3];
    float*       O[3];
};

#define AS_STR 36
#define BS_STR 68
#define GEMM_SMEM ((3*64*AS_STR + 3*32*BS_STR)*4)

template<bool RELU, bool RES>
__global__ __launch_bounds__(256)
void gemm_kernel(GArgs ga, const float* __restrict__ Rres, float* __restrict__ OutB,
                 int K, int N, int bnshift) {
    extern __shared__ __align__(16) float dsm[];
    float* As = dsm;                     // [3][64*AS_STR]
    float* Bs = dsm + 3*64*AS_STR;       // [3][32*BS_STR]

    int tid = threadIdx.x;
    int w   = tid >> 5;
    int bx  = blockIdx.x;
    int sel = bx >> bnshift;
    int bn  = bx & ((1 << bnshift) - 1);
    int bm  = blockIdx.y;
    int bz  = blockIdx.z;
    bool first = (bz == 0);

    int lda = K * gridDim.z;
    const float* Abase = ga.A[sel] + (size_t)(bm*64)*lda + (size_t)bz*K;
    const float* Wbase = ga.W[sel] + (size_t)bz*K*N + bn*64;
    const float* bias  = ga.bi[sel];
    float*       Out   = first ? ga.O[sel] : OutB;

    int wm = w & 3;      // 4 row blocks of 16
    int wn = w >> 2;     // 2 col blocks of 32

    wmma::fragment<wmma::accumulator,16,16,8,float> c[2];
    wmma::fill_fragment(c[0], 0.0f);
    wmma::fill_fragment(c[1], 0.0f);

    auto stage = [&](int t, int buf) {
        float* Ab = As + buf*64*AS_STR;
        float* Bb = Bs + buf*32*BS_STR;
        const float* Ag = Abase + t*32;
        #pragma unroll
        for (int i = 0; i < 2; i++) {
            int s = tid + i*256;
            int r = s >> 3, c4 = s & 7;
            cpa16(&Ab[r*AS_STR + c4*4], Ag + (size_t)r*lda + c4*4);
        }
        const float* Wg = Wbase + (size_t)(t*32)*N;
        #pragma unroll
        for (int i = 0; i < 2; i++) {
            int s = tid + i*256;
            int r = s >> 4, c4 = s & 15;
            cpa16(&Bb[r*BS_STR + c4*4], Wg + (size_t)r*N + c4*4);
        }
        cpa_commit();
    };

    int T = K >> 5;
    stage(0, 0);
    if (T > 1) stage(1, 1);

    for (int t = 0; t < T; t++) {
        int buf = t % 3;
        if (t + 2 < T) { stage(t+2, (t+2)%3); cpa_wait<2>(); }
        else if (t + 1 < T) cpa_wait<1>();
        else cpa_wait<0>();
        __syncthreads();

        float* Ab = As + buf*64*AS_STR;
        float* Bb = Bs + buf*32*BS_STR;
        #pragma unroll
        for (int kk = 0; kk < 4; kk++) {
            wmma::fragment<wmma::matrix_a,16,16,8,wmma::precision::tf32,wmma::row_major> a;
            wmma::load_matrix_sync(a, &Ab[(wm*16)*AS_STR + kk*8], AS_STR);
            #pragma unroll
            for (int e = 0; e < a.num_elements; e++)
                a.x[e] = wmma::__float_to_tf32(a.x[e]);
            #pragma unroll
            for (int j = 0; j < 2; j++) {
                wmma::fragment<wmma::matrix_b,16,16,8,wmma::precision::tf32,wmma::row_major> bf;
                wmma::load_matrix_sync(bf, &Bb[(kk*8)*BS_STR + wn*32 + j*16], BS_STR);
                #pragma unroll
                for (int e = 0; e < bf.num_elements; e++)
                    bf.x[e] = wmma::__float_to_tf32(bf.x[e]);
                wmma::mma_sync(c[j], a, bf, c[j]);
            }
        }
        __syncthreads();
    }

    // epilogue via smem: Cs [64][68] fits in As area (3*64*36 = 6912 >= 4352)
    float* Cs = As;
    #pragma unroll
    for (int j = 0; j < 2; j++)
        wmma::store_matrix_sync(&Cs[(wm*16)*68 + wn*32 + j*16], c[j], 68,
                                wmma::mem_row_major);
    __syncthreads();

    #pragma unroll
    for (int i = 0; i < 4; i++) {
        int s = tid + i*256;
        int r = s >> 4, c4 = s & 15;
        int gr = bm*64 + r;
        int gc = bn*64 + c4*4;
        float4 v  = *(float4*)&Cs[r*68 + c4*4];
        if (first) {
            float4 bb = *(const float4*)&bias[gc];
            v.x += bb.x; v.y += bb.y; v.z += bb.z; v.w += bb.w;
            if (RES) {
                float4 rr = *(const float4*)&Rres[(size_t)gr*N + gc];
                v.x += rr.x; v.y += rr.y; v.z += rr.z; v.w += rr.w;
            }
        }
        if (RELU) {
            v.x = fmaxf(v.x, 0.f); v.y = fmaxf(v.y, 0.f);
            v.z = fmaxf(v.z, 0.f); v.w = fmaxf(v.w, 0.f);
        }
        *(float4*)&Out[(size_t)gr*N + gc] = v;
    }
}

// ---------------- fused attention (tf32, no-max softmax, cp.async dbuf) -------------
__global__ __launch_bounds__(256)
void attn_kernel(const float* __restrict__ Qg, const float* __restrict__ Kg,
                 const float* __restrict__ Vg, float* __restrict__ Og,
                 const int* __restrict__ mask, int Lk, int causal) {
    extern __shared__ __align__(16) float sm[];
    float* Qs    = sm;                     // 64*36
    float* Ks0   = sm + 2304;
    float* Ks1   = sm + 4608;
    float* Vs0   = sm + 6912;
    float* Vs1   = sm + 9216;
    float* Ss    = sm + 11520;             // 64*68
    float* rs4   = sm + 15872;             // 256
    float* rowsum= sm + 16128;             // 64
    int*   smask = (int*)(sm + 16192);     // 2*64

    float* KsB[2] = {Ks0, Ks1};
    float* VsB[2] = {Vs0, Vs1};

    int tid = threadIdx.x;
    int w   = tid >> 5;
    // heavy causal tiles first (qt large) to kill the wave tail
    int qt  = causal ? (gridDim.x - 1 - blockIdx.x) : blockIdx.x;
    int h = blockIdx.y, b = blockIdx.z;
    int q0  = qt*64;

    const float* Qp = Qg + ((size_t)(b*SEQ + q0))*DMODEL + h*DHEAD;
    #pragma unroll
    for (int i = 0; i < 2; i++) {
        int s = tid + i*256;
        int r = s >> 3, c4 = s & 7;
        *(float4*)&Qs[r*36 + c4*4] = *(const float4*)&Qp[(size_t)r*DMODEL + c4*4];
    }
    if (tid < 64) rowsum[tid] = 0.f;

    const float* Kbase = Kg + (size_t)b*Lk*DMODEL + h*DHEAD;
    const float* Vbase = Vg + (size_t)b*Lk*DMODEL + h*DHEAD;

    auto stage_kv = [&](int kt, int buf) {
        int k0 = kt*64;
        const float* Kp = Kbase + (size_t)k0*DMODEL;
        const float* Vp = Vbase + (size_t)k0*DMODEL;
        #pragma unroll
        for (int i = 0; i < 2; i++) {
            int s = tid + i*256;
            int r = s >> 3, c4 = s & 7;
            cpa16(&KsB[buf][r*36 + c4*4], Kp + (size_t)r*DMODEL + c4*4);
            cpa16(&VsB[buf][r*36 + c4*4], Vp + (size_t)r*DMODEL + c4*4);
        }
        if (tid < 64) smask[buf*64 + tid] = mask[b*Lk + k0 + tid];
        cpa_commit();
    };

    __syncthreads();   // Qs visible

    int smi = w & 3;
    int sn0 = (w >> 2) * 2;
    wmma::fragment<wmma::matrix_a,16,16,8,wmma::precision::tf32,wmma::row_major> qa[4];
    #pragma unroll
    for (int kk = 0; kk < 4; kk++) {
        wmma::load_matrix_sync(qa[kk], &Qs[smi*16*36 + kk*8], 36);
        #pragma unroll
        for (int e = 0; e < qa[kk].num_elements; e++)
            qa[kk].x[e] = wmma::__float_to_tf32(qa[kk].x[e]);
    }
    int omi = w & 3, oni = w >> 2;
    wmma::fragment<wmma::accumulator,16,16,8,float> of;
    wmma::fill_fragment(of, 0.0f);

    const float inv_sqrt_dk = 0.17677669529663689f;
    int ktend = causal ? (qt + 1) : (Lk >> 6);

    stage_kv(0, 0);

    for (int kt = 0; kt < ktend; kt++) {
        int buf = kt & 1;
        int k0  = kt*64;
        if (kt + 1 < ktend) {
            stage_kv(kt+1, buf ^ 1);
            cpa_wait<1>();
        } else {
            cpa_wait<0>();
        }
        __syncthreads();

        float* Ks = KsB[buf];
        float* Vs = VsB[buf];

        // S = Q @ K^T
        #pragma unroll
        for (int nj = 0; nj < 2; nj++) {
            int n = sn0 + nj;
            wmma::fragment<wmma::accumulator,16,16,8,float> cf;
            wmma::fill_fragment(cf, 0.0f);
            #pragma unroll
            for (int kk = 0; kk < 4; kk++) {
                wmma::fragment<wmma::matrix_b,16,16,8,wmma::precision::tf32,wmma::col_major> kb;
                wmma::load_matrix_sync(kb, &Ks[n*16*36 + kk*8], 36);
                #pragma unroll
                for (int e = 0; e < kb.num_elements; e++)
                    kb.x[e] = wmma::__float_to_tf32(kb.x[e]);
                wmma::mma_sync(cf, qa[kk], kb, cf);
            }
            wmma::store_matrix_sync(&Ss[smi*16*68 + n*16], cf, 68, wmma::mem_row_major);
        }
        __syncthreads();

        // P = exp(scale*S) with mask; row partial sums
        {
            int r  = tid >> 2;
            int g4 = tid & 3;
            int qi = q0 + r;
            float part = 0.f;
            #pragma unroll
            for (int cc = 0; cc < 16; cc++) {
                int c  = g4*16 + cc;
                int kj = k0 + c;
                float sc = Ss[r*68 + c] * inv_sqrt_dk;
                bool m = (causal && kj > qi) || (smask[buf*64 + c] != 0);
                float p = m ? 0.0f : __expf(sc);
                Ss[r*68 + c] = p;
                part += p;
            }
            rs4[r*4 + g4] = part;
        }
        __syncthreads();
        if (tid < 64)
            rowsum[tid] += rs4[tid*4] + rs4[tid*4+1] + rs4[tid*4+2] + rs4[tid*4+3];

        // O += P @ V
        #pragma unroll
        for (int kk = 0; kk < 8; kk++) {
            wmma::fragment<wmma::matrix_a,16,16,8,wmma::precision::tf32,wmma::row_major> pa;
            wmma::load_matrix_sync(pa, &Ss[omi*16*68 + kk*8], 68);
            #pragma unroll
            for (int e = 0; e < pa.num_elements; e++)
                pa.x[e] = wmma::__float_to_tf32(pa.x[e]);
            wmma::fragment<wmma::matrix_b,16,16,8,wmma::precision::tf32,wmma::row_major> vb;
            wmma::load_matrix_sync(vb, &Vs[(kk*8)*36 + oni*16], 36);
            #pragma unroll
            for (int e = 0; e < vb.num_elements; e++)
                vb.x[e] = wmma::__float_to_tf32(vb.x[e]);
            wmma::mma_sync(of, pa, vb, of);
        }
        __syncthreads();
    }

    wmma::store_matrix_sync(&Ss[omi*16*36 + oni*16], of, 36, wmma::mem_row_major);
    __syncthreads();
    {
        int r  = tid >> 2;
        int g4 = tid & 3;
        float rinv = 1.0f / rowsum[r];
        float* op = Og + ((size_t)(b*SEQ + q0 + r))*DMODEL + h*DHEAD + g4*8;
        #pragma unroll
        for (int cc = 0; cc < 8; cc++)
            op[cc] = Ss[r*36 + g4*8 + cc] * rinv;
    }
}

#define ATTN_SMEM 65536

// ---------------- orchestration ----------------
extern "C" void kernel_launch(void* const* d_in, const int* in_sizes, int n_in,
                              void* d_out, int out_size) {
    const float* enc      = (const float*)d_in[0];
    const float* dec      = (const float*)d_in[1];
    const int*   enc_mask = (const int*)  d_in[2];
    const int*   dec_mask = (const int*)  d_in[3];
    const float* W_tgt    = (const float*)d_in[4];
    const float* b_tgt    = (const float*)d_in[5];
    const float* sa_Wq = (const float*)d_in[6];  const float* sa_bq = (const float*)d_in[7];
    const float* sa_Wk = (const float*)d_in[8];  const float* sa_bk = (const float*)d_in[9];
    const float* sa_Wv = (const float*)d_in[10]; const float* sa_bv = (const float*)d_in[11];
    const float* sa_Wo = (const float*)d_in[12]; const float* sa_bo = (const float*)d_in[13];
    const float* sa_g  = (const float*)d_in[14]; const float* sa_b  = (const float*)d_in[15];
    const float* ca_Wq = (const float*)d_in[16]; const float* ca_bq = (const float*)d_in[17];
    const float* ca_Wk = (const float*)d_in[18]; const float* ca_bk = (const float*)d_in[19];
    const float* ca_Wv = (const float*)d_in[20]; const float* ca_bv = (const float*)d_in[21];
    const float* ca_Wo = (const float*)d_in[22]; const float* ca_bo = (const float*)d_in[23];
    const float* ca_g  = (const float*)d_in[24]; const float* ca_b  = (const float*)d_in[25];
    const float* ff_W1 = (const float*)d_in[26]; const float* ff_b1 = (const float*)d_in[27];
    const float* ff_W2 = (const float*)d_in[28]; const float* ff_b2 = (const float*)d_in[29];
    const float* ff_g  = (const float*)d_in[30]; const float* ff_b  = (const float*)d_in[31];

    float* scratch = nullptr;
    cudaGetSymbolAddress((void**)&scratch, g_scratch);
    float* X = scratch + OFF_X;
    float* T = scratch + OFF_T;
    float* Q = scratch + OFF_Q;
    float* K = scratch + OFF_K;
    float* V = scratch + OFF_V;
    float* C = scratch + OFF_C;
    float* Hh = scratch + OFF_H;

    cudaFuncSetAttribute(attn_kernel, cudaFuncAttributeMaxDynamicSharedMemorySize, ATTN_SMEM);
    cudaFuncSetAttribute(gemm_kernel<false,false>, cudaFuncAttributeMaxDynamicSharedMemorySize, GEMM_SMEM);
    cudaFuncSetAttribute(gemm_kernel<false,true >, cudaFuncAttributeMaxDynamicSharedMemorySize, GEMM_SMEM);
    cudaFuncSetAttribute(gemm_kernel<true ,false>, cudaFuncAttributeMaxDynamicSharedMemorySize, GEMM_SMEM);

    dim3 blkG(256), blkA(256), blkR(256);
    dim3 g_rows(TOK);
    dim3 g_qkv(12, 64);
    dim3 g_256(4, 64);
    dim3 g_1024(16, 64);
    dim3 g_w2(4, 64, 2);          // split-K x2
    dim3 g_attn(SEQ/64, NHEAD, BATCH);

    embed_kernel<<<g_rows, blkR>>>(dec, W_tgt, b_tgt, X);

    const int WD  = DMODEL*DMODEL;
    const int W1S = DMODEL*DFF;
    const int W2S = DFF*DMODEL;

    for (int i = 0; i < NLAYER; i++) {
        // ---- self attention ----
        {
            GArgs ga;
            ga.A[0]=X; ga.A[1]=X; ga.A[2]=X;
            ga.W[0]=sa_Wq+i*WD; ga.W[1]=sa_Wk+i*WD; ga.W[2]=sa_Wv+i*WD;
            ga.bi[0]=sa_bq+i*DMODEL; ga.bi[1]=sa_bk+i*DMODEL; ga.bi[2]=sa_bv+i*DMODEL;
            ga.O[0]=Q; ga.O[1]=K; ga.O[2]=V;
            gemm_kernel<false,false><<<g_qkv, blkG, GEMM_SMEM>>>(ga, nullptr, nullptr, DMODEL, DMODEL, 2);
        }
        attn_kernel<<<g_attn, blkA, ATTN_SMEM>>>(Q, K, V, C, dec_mask, SEQ, 1);
        {
            GArgs ga{};
            ga.A[0]=C; ga.W[0]=sa_Wo+i*WD; ga.bi[0]=sa_bo+i*DMODEL; ga.O[0]=T;
            gemm_kernel<false,true><<<g_256, blkG, GEMM_SMEM>>>(ga, X, nullptr, DMODEL, DMODEL, 2);
        }
        ln_kernel<<<g_rows, blkR>>>(T, nullptr, sa_g+i*DMODEL, sa_b+i*DMODEL, X, 0);

        // ---- cross attention ----
        {
            GArgs ga;
            ga.A[0]=X; ga.A[1]=enc; ga.A[2]=enc;
            ga.W[0]=ca_Wq+i*WD; ga.W[1]=ca_Wk+i*WD; ga.W[2]=ca_Wv+i*WD;
            ga.bi[0]=ca_bq+i*DMODEL; ga.bi[1]=ca_bk+i*DMODEL; ga.bi[2]=ca_bv+i*DMODEL;
            ga.O[0]=Q; ga.O[1]=K; ga.O[2]=V;
            gemm_kernel<false,false><<<g_qkv, blkG, GEMM_SMEM>>>(ga, nullptr, nullptr, DMODEL, DMODEL, 2);
        }
        attn_kernel<<<g_attn, blkA, ATTN_SMEM>>>(Q, K, V, C, enc_mask, SEQ, 0);
        {
            GArgs ga{};
            ga.A[0]=C; ga.W[0]=ca_Wo+i*WD; ga.bi[0]=ca_bo+i*DMODEL; ga.O[0]=T;
            gemm_kernel<false,true><<<g_256, blkG, GEMM_SMEM>>>(ga, X, nullptr, DMODEL, DMODEL, 2);
        }
        ln_kernel<<<g_rows, blkR>>>(T, nullptr, ca_g+i*DMODEL, ca_b+i*DMODEL, X, 0);

        // ---- FFN ----
        {
            GArgs ga{};
            ga.A[0]=X; ga.W[0]=ff_W1+i*W1S; ga.bi[0]=ff_b1+i*DFF; ga.O[0]=Hh;
            gemm_kernel<true,false><<<g_1024, blkG, GEMM_SMEM>>>(ga, nullptr, nullptr, DMODEL, DFF, 4);
        }
        {
            GArgs ga{};
            ga.A[0]=Hh; ga.W[0]=ff_W2+i*W2S; ga.bi[0]=ff_b2+i*DMODEL; ga.O[0]=T;
            // split-K x2: z=0 -> T (with bias+residual), z=1 -> Q (partial)
            gemm_kernel<false,true><<<g_w2, blkG, GEMM_SMEM>>>(ga, X, Q, DFF/2, DMODEL, 2);
        }
        ln_kernel<<<g_rows, blkR>>>(T, Q, ff_g+i*DMODEL, ff_b+i*DMODEL, X, (i < NLAYER-1) ? 1 : 0);
    }

    cudaMemcpyAsync(d_out, X, (size_t)TOK*DMODEL*sizeof(float),
                    cudaMemcpyDeviceToDevice);
}

// round 4
// speedup vs baseline: 1.7118x; 1.7118x over previous
#include <cuda_runtime.h>
#include <cuda_fp16.h>
#include <mma.h>
#include <math.h>

using namespace nvcuda;

#define BATCH   4
#define SEQ     1024
#define DMODEL  256
#define NHEAD   8
#define DHEAD   32
#define DFF     1024
#define NLAYER  6
#define TOK     (BATCH*SEQ)
#define TD      (TOK*DMODEL)          // 1,048,576

// fp32 scratch: X (residual stream), T (pre-LN temp)
__device__ __align__(16) float  g_fscratch[2*TD];
// half scratch: Xh, ENCh, Qh, Kh, Vh, Ch, Hh(4M), weights(6.29M) = 16M halves
__device__ __align__(16) __half g_hscratch[16*1024*1024];

#define OFF_X   0
#define OFF_T   TD

#define HOFF_XH  0
#define HOFF_ENC (1*TD)
#define HOFF_Q   (2*TD)
#define HOFF_K   (3*TD)
#define HOFF_V   (4*TD)
#define HOFF_C   (5*TD)
#define HOFF_H   (6*TD)               // TOK*DFF = 4*TD
#define HOFF_W   (10*TD)
#define WSEG     393216               // NL*256*256

// ---------------- cp.async helpers ----------------
__device__ __forceinline__ void cpa16(void* dst, const void* src) {
    unsigned s = (unsigned)__cvta_generic_to_shared(dst);
    asm volatile("cp.async.cg.shared.global [%0], [%1], 16;\n" :: "r"(s), "l"(src));
}
__device__ __forceinline__ void cpa_commit() {
    asm volatile("cp.async.commit_group;\n");
}
template<int N>
__device__ __forceinline__ void cpa_wait() {
    asm volatile("cp.async.wait_group %0;\n" :: "n"(N));
}

// ---------------- fp32 -> fp16 convert ----------------
__global__ void cvt_kernel(const float* __restrict__ s, __half* __restrict__ d, int n) {
    int i = (blockIdx.x*blockDim.x + threadIdx.x)*4;
    if (i < n) {
        float4 v = *(const float4*)&s[i];
        __half2* o = (__half2*)&d[i];
        o[0] = __floats2half2_rn(v.x, v.y);
        o[1] = __floats2half2_rn(v.z, v.w);
    }
}

// ---------------- positional embedding ----------------
__device__ __forceinline__ float pe_val(int l, int d) {
    int j = d & 127;
    double e = -(2.0*(double)j/256.0) * 9.210340371976184;  // ln(10000)
    float invf = (float)exp(e);
    float arg = (float)l * invf;
    return (d < 128) ? sinf(arg) : cosf(arg);
}

// ---------------- embed (+PE layer 0), dual fp32/fp16 out ----------------
__global__ void embed_kernel(const float* __restrict__ dec,
                             const float* __restrict__ W,
                             const float* __restrict__ b,
                             float* __restrict__ x, __half* __restrict__ xh) {
    int row = blockIdx.x;
    int d   = threadIdx.x;
    const float* in = dec + row*3;
    float acc = b[d] + in[0]*W[d] + in[1]*W[DMODEL+d] + in[2]*W[2*DMODEL+d]
              + pe_val(row & (SEQ-1), d);
    x [row*DMODEL + d] = acc;
    xh[row*DMODEL + d] = __float2half(acc);
}

// ---------------- LayerNorm, dual out, optional +PE ----------------
__global__ void ln_kernel(const float* __restrict__ t,
                          const float* __restrict__ g,
                          const float* __restrict__ b,
                          float* __restrict__ out, __half* __restrict__ outh,
                          int addpe) {
    int row = blockIdx.x;
    int d   = threadIdx.x;
    float v = t[row*DMODEL + d];

    __shared__ float red[8];
    __shared__ float stats[2];

    float s = v;
    #pragma unroll
    for (int o = 16; o; o >>= 1) s += __shfl_xor_sync(0xffffffffu, s, o);
    if ((d & 31) == 0) red[d >> 5] = s;
    __syncthreads();
    if (d == 0) {
        float m = 0.f;
        #pragma unroll
        for (int i = 0; i < 8; i++) m += red[i];
        stats[0] = m * (1.0f/DMODEL);
    }
    __syncthreads();
    float mean = stats[0];
    float dv = v - mean;
    float s2 = dv*dv;
    #pragma unroll
    for (int o = 16; o; o >>= 1) s2 += __shfl_xor_sync(0xffffffffu, s2, o);
    if ((d & 31) == 0) red[d >> 5] = s2;
    __syncthreads();
    if (d == 0) {
        float var = 0.f;
        #pragma unroll
        for (int i = 0; i < 8; i++) var += red[i];
        stats[1] = rsqrtf(var * (1.0f/DMODEL) + 1e-5f);
    }
    __syncthreads();
    float o = dv * stats[1] * g[d] + b[d];
    if (addpe) o += pe_val(row & (SEQ-1), d);
    out [row*DMODEL + d] = o;
    outh[row*DMODEL + d] = __float2half(o);
}

// ---------------- fp16 wmma GEMM: 64x64x32, 256 thr, 3-stage, 1 sync/iter ----------
struct GArgs {
    const __half* A[3];
    const __half* W[3];
    const float*  bi[3];
    void*         O[3];
};

#define AS_H 40     // half stride, A tiles (64 rows x 32)
#define BS_H 72     // half stride, B tiles (32 rows x 64)
#define GEMM_SMEM ((3*64*AS_H + 3*32*BS_H)*2)   // 29184 B

template<bool RELU, bool RES, bool OUTH>
__global__ __launch_bounds__(256)
void gemm_kernel(GArgs ga, const float* __restrict__ Rres,
                 int K, int N, int bnshift) {
    extern __shared__ __align__(16) char dsmc[];
    __half* As = (__half*)dsmc;            // 3 x 64*AS_H
    __half* Bs = As + 3*64*AS_H;           // 3 x 32*BS_H

    int tid = threadIdx.x;
    int w   = tid >> 5;
    int bx  = blockIdx.x;
    int sel = bx >> bnshift;
    int bn  = bx & ((1 << bnshift) - 1);
    int bm  = blockIdx.y;

    const __half* Abase = ga.A[sel] + (size_t)(bm*64)*K;
    const __half* Wbase = ga.W[sel] + bn*64;
    const float*  bias  = ga.bi[sel];

    int wm = w & 3;      // 4 row blocks of 16
    int wn = w >> 2;     // 2 col blocks of 32

    wmma::fragment<wmma::accumulator,16,16,16,float> c[2];
    wmma::fill_fragment(c[0], 0.0f);
    wmma::fill_fragment(c[1], 0.0f);

    auto stage = [&](int t, int buf) {
        __half* Ab = As + buf*64*AS_H;
        __half* Bb = Bs + buf*32*BS_H;
        const __half* Ag = Abase + t*32;
        {   // 64 rows x 4 chunks of 8 halves
            int r = tid >> 2, c8 = tid & 3;
            cpa16(&Ab[r*AS_H + c8*8], Ag + (size_t)r*K + c8*8);
        }
        const __half* Wg = Wbase + (size_t)(t*32)*N;
        {   // 32 rows x 8 chunks of 8 halves
            int r = tid >> 3, c8 = tid & 7;
            cpa16(&Bb[r*BS_H + c8*8], Wg + (size_t)r*N + c8*8);
        }
        cpa_commit();
    };

    int T = K >> 5;
    stage(0, 0);
    if (T > 1) stage(1, 1);

    for (int t = 0; t < T; t++) {
        if (t + 1 < T) cpa_wait<1>(); else cpa_wait<0>();
        __syncthreads();            // group-t visible; all warps done mma(t-1)
        if (t + 2 < T) stage(t+2, (t+2)%3);

        int buf = t % 3;
        __half* Ab = As + buf*64*AS_H;
        __half* Bb = Bs + buf*32*BS_H;
        #pragma unroll
        for (int kk = 0; kk < 2; kk++) {
            wmma::fragment<wmma::matrix_a,16,16,16,__half,wmma::row_major> a;
            wmma::load_matrix_sync(a, &Ab[(wm*16)*AS_H + kk*16], AS_H);
            #pragma unroll
            for (int j = 0; j < 2; j++) {
                wmma::fragment<wmma::matrix_b,16,16,16,__half,wmma::row_major> bf;
                wmma::load_matrix_sync(bf, &Bb[(kk*16)*BS_H + wn*32 + j*16], BS_H);
                wmma::mma_sync(c[j], a, bf, c[j]);
            }
        }
    }
    __syncthreads();   // protect smem before epilogue reuse

    float* Cs = (float*)dsmc;   // 64 x 68 floats (17408 B <= 29184)
    #pragma unroll
    for (int j = 0; j < 2; j++)
        wmma::store_matrix_sync(&Cs[(wm*16)*68 + wn*32 + j*16], c[j], 68,
                                wmma::mem_row_major);
    __syncthreads();

    #pragma unroll
    for (int i = 0; i < 4; i++) {
        int s = tid + i*256;
        int r = s >> 4, c4 = s & 15;
        int gr = bm*64 + r;
        int gc = bn*64 + c4*4;
        float4 v  = *(float4*)&Cs[r*68 + c4*4];
        float4 bb = *(const float4*)&bias[gc];
        v.x += bb.x; v.y += bb.y; v.z += bb.z; v.w += bb.w;
        if (RES) {
            float4 rr = *(const float4*)&Rres[(size_t)gr*N + gc];
            v.x += rr.x; v.y += rr.y; v.z += rr.z; v.w += rr.w;
        }
        if (RELU) {
            v.x = fmaxf(v.x, 0.f); v.y = fmaxf(v.y, 0.f);
            v.z = fmaxf(v.z, 0.f); v.w = fmaxf(v.w, 0.f);
        }
        if (OUTH) {
            __half2* op = (__half2*)((__half*)ga.O[sel] + (size_t)gr*N + gc);
            op[0] = __floats2half2_rn(v.x, v.y);
            op[1] = __floats2half2_rn(v.z, v.w);
        } else {
            *(float4*)((float*)ga.O[sel] + (size_t)gr*N + gc) = v;
        }
    }
}

// ---------------- fused attention, fp16 MMAs, no-max softmax ----------------
// smem layout (bytes):
//  Qs    @0      : 64x40 half  = 5120
//  Ks0   @5120   : 5120    Ks1 @10240 : 5120
//  Vs0   @15360  : 5120    Vs1 @20480 : 5120
//  Ss f32@25600  : 64x68x4 = 17408
//  Ps h16@43008  : 64x72x2 = 9216
//  rs4   @52224  : 1024
//  rowsum@53248  : 256
//  smask @53504  : 512
#define ATTN_SMEM 54016

__global__ __launch_bounds__(256)
void attn_kernel(const __half* __restrict__ Qg, const __half* __restrict__ Kg,
                 const __half* __restrict__ Vg, __half* __restrict__ Og,
                 const int* __restrict__ mask, int Lk, int causal) {
    extern __shared__ __align__(16) char smc[];
    __half* Qs    = (__half*)smc;
    __half* KsB[2] = {(__half*)(smc + 5120),  (__half*)(smc + 10240)};
    __half* VsB[2] = {(__half*)(smc + 15360), (__half*)(smc + 20480)};
    float*  Ss    = (float*)(smc + 25600);
    __half* Ps    = (__half*)(smc + 43008);
    float*  rs4   = (float*)(smc + 52224);
    float*  rowsum= (float*)(smc + 53248);
    int*    smask = (int*)  (smc + 53504);

    int tid = threadIdx.x;
    int w   = tid >> 5;
    int qt  = blockIdx.x, h = blockIdx.y, b = blockIdx.z;
    int q0  = qt*64;

    const __half* Qp = Qg + ((size_t)(b*SEQ + q0))*DMODEL + h*DHEAD;
    {   // 64 rows x 4 chunks of 8 halves
        int r = tid >> 2, c8 = tid & 3;
        *(float4*)&Qs[r*40 + c8*8] = *(const float4*)&Qp[(size_t)r*DMODEL + c8*8];
    }
    if (tid < 64) rowsum[tid] = 0.f;

    const __half* Kbase = Kg + (size_t)b*Lk*DMODEL + h*DHEAD;
    const __half* Vbase = Vg + (size_t)b*Lk*DMODEL + h*DHEAD;

    auto stage_kv = [&](int kt, int buf) {
        int k0 = kt*64;
        const __half* Kp = Kbase + (size_t)k0*DMODEL;
        const __half* Vp = Vbase + (size_t)k0*DMODEL;
        int r = tid >> 2, c8 = tid & 3;
        cpa16(&KsB[buf][r*40 + c8*8], Kp + (size_t)r*DMODEL + c8*8);
        cpa16(&VsB[buf][r*40 + c8*8], Vp + (size_t)r*DMODEL + c8*8);
        if (tid < 64) smask[buf*64 + tid] = mask[b*Lk + k0 + tid];
        cpa_commit();
    };

    __syncthreads();   // Qs visible

    int smi = w & 3;
    int sn0 = (w >> 2) * 2;
    wmma::fragment<wmma::matrix_a,16,16,16,__half,wmma::row_major> qa[2];
    #pragma unroll
    for (int kk = 0; kk < 2; kk++)
        wmma::load_matrix_sync(qa[kk], &Qs[smi*16*40 + kk*16], 40);

    int omi = w & 3, oni = w >> 2;
    wmma::fragment<wmma::accumulator,16,16,16,float> of;
    wmma::fill_fragment(of, 0.0f);

    const float inv_sqrt_dk = 0.17677669529663689f;
    int ktend = causal ? (qt + 1) : (Lk >> 6);

    stage_kv(0, 0);

    for (int kt = 0; kt < ktend; kt++) {
        int buf = kt & 1;
        int k0  = kt*64;
        if (kt + 1 < ktend) {
            stage_kv(kt+1, buf ^ 1);
            cpa_wait<1>();
        } else {
            cpa_wait<0>();
        }
        __syncthreads();

        __half* Ks = KsB[buf];
        __half* Vs = VsB[buf];

        // S = Q @ K^T (64x64)
        #pragma unroll
        for (int nj = 0; nj < 2; nj++) {
            int n = sn0 + nj;
            wmma::fragment<wmma::accumulator,16,16,16,float> cf;
            wmma::fill_fragment(cf, 0.0f);
            #pragma unroll
            for (int kk = 0; kk < 2; kk++) {
                wmma::fragment<wmma::matrix_b,16,16,16,__half,wmma::col_major> kb;
                wmma::load_matrix_sync(kb, &Ks[n*16*40 + kk*16], 40);
                wmma::mma_sync(cf, qa[kk], kb, cf);
            }
            wmma::store_matrix_sync(&Ss[smi*16*68 + n*16], cf, 68, wmma::mem_row_major);
        }
        __syncthreads();

        // P = exp(scale*S) with mask -> half; row partial sums (fp32)
        {
            int r  = tid >> 2;
            int g4 = tid & 3;
            int qi = q0 + r;
            float part = 0.f;
            #pragma unroll
            for (int cc = 0; cc < 16; cc++) {
                int c  = g4*16 + cc;
                int kj = k0 + c;
                float sc = Ss[r*68 + c] * inv_sqrt_dk;
                bool m = (causal && kj > qi) || (smask[buf*64 + c] != 0);
                float p = m ? 0.0f : __expf(sc);
                Ps[r*72 + c] = __float2half(p);
                part += p;
            }
            rs4[r*4 + g4] = part;
        }
        __syncthreads();
        if (tid < 64)
            rowsum[tid] += rs4[tid*4] + rs4[tid*4+1] + rs4[tid*4+2] + rs4[tid*4+3];

        // O += P @ V (64x64 @ 64x32)
        #pragma unroll
        for (int kk = 0; kk < 4; kk++) {
            wmma::fragment<wmma::matrix_a,16,16,16,__half,wmma::row_major> pa;
            wmma::load_matrix_sync(pa, &Ps[omi*16*72 + kk*16], 72);
            wmma::fragment<wmma::matrix_b,16,16,16,__half,wmma::row_major> vb;
            wmma::load_matrix_sync(vb, &Vs[(kk*16)*40 + oni*16], 40);
            wmma::mma_sync(of, pa, vb, of);
        }
        __syncthreads();
    }

    // write out: of -> Ss as [64][36] f32, scale by 1/rowsum, store half
    wmma::store_matrix_sync(&Ss[omi*16*36 + oni*16], of, 36, wmma::mem_row_major);
    __syncthreads();
    {
        int r  = tid >> 2;
        int g4 = tid & 3;
        float rinv = 1.0f / rowsum[r];
        __half* op = Og + ((size_t)(b*SEQ + q0 + r))*DMODEL + h*DHEAD + g4*8;
        #pragma unroll
        for (int cc = 0; cc < 8; cc++)
            op[cc] = __float2half(Ss[r*36 + g4*8 + cc] * rinv);
    }
}

// ---------------- orchestration ----------------
extern "C" void kernel_launch(void* const* d_in, const int* in_sizes, int n_in,
                              void* d_out, int out_size) {
    const float* enc      = (const float*)d_in[0];
    const float* dec      = (const float*)d_in[1];
    const int*   enc_mask = (const int*)  d_in[2];
    const int*   dec_mask = (const int*)  d_in[3];
    const float* W_tgt    = (const float*)d_in[4];
    const float* b_tgt    = (const float*)d_in[5];
    const float* sa_Wq = (const float*)d_in[6];  const float* sa_bq = (const float*)d_in[7];
    const float* sa_Wk = (const float*)d_in[8];  const float* sa_bk = (const float*)d_in[9];
    const float* sa_Wv = (const float*)d_in[10]; const float* sa_bv = (const float*)d_in[11];
    const float* sa_Wo = (const float*)d_in[12]; const float* sa_bo = (const float*)d_in[13];
    const float* sa_g  = (const float*)d_in[14]; const float* sa_b  = (const float*)d_in[15];
    const float* ca_Wq = (const float*)d_in[16]; const float* ca_bq = (const float*)d_in[17];
    const float* ca_Wk = (const float*)d_in[18]; const float* ca_bk = (const float*)d_in[19];
    const float* ca_Wv = (const float*)d_in[20]; const float* ca_bv = (const float*)d_in[21];
    const float* ca_Wo = (const float*)d_in[22]; const float* ca_bo = (const float*)d_in[23];
    const float* ca_g  = (const float*)d_in[24]; const float* ca_b  = (const float*)d_in[25];
    const float* ff_W1 = (const float*)d_in[26]; const float* ff_b1 = (const float*)d_in[27];
    const float* ff_W2 = (const float*)d_in[28]; const float* ff_b2 = (const float*)d_in[29];
    const float* ff_g  = (const float*)d_in[30]; const float* ff_b  = (const float*)d_in[31];

    float* fs = nullptr;
    __half* hs = nullptr;
    cudaGetSymbolAddress((void**)&fs, g_fscratch);
    cudaGetSymbolAddress((void**)&hs, g_hscratch);
    float* X = fs + OFF_X;
    float* T = fs + OFF_T;
    __half* Xh  = hs + HOFF_XH;
    __half* ENCh= hs + HOFF_ENC;
    __half* Qh  = hs + HOFF_Q;
    __half* Kh  = hs + HOFF_K;
    __half* Vh  = hs + HOFF_V;
    __half* Ch  = hs + HOFF_C;
    __half* Hh  = hs + HOFF_H;
    __half* Wh  = hs + HOFF_W;

    __half* hsaWq = Wh + 0*WSEG;
    __half* hsaWk = Wh + 1*WSEG;
    __half* hsaWv = Wh + 2*WSEG;
    __half* hsaWo = Wh + 3*WSEG;
    __half* hcaWq = Wh + 4*WSEG;
    __half* hcaWk = Wh + 5*WSEG;
    __half* hcaWv = Wh + 6*WSEG;
    __half* hcaWo = Wh + 7*WSEG;
    __half* hffW1 = Wh + 8*WSEG;
    __half* hffW2 = hffW1 + NLAYER*DMODEL*DFF;

    cudaFuncSetAttribute(attn_kernel, cudaFuncAttributeMaxDynamicSharedMemorySize, ATTN_SMEM);
    cudaFuncSetAttribute(gemm_kernel<false,false,true >, cudaFuncAttributeMaxDynamicSharedMemorySize, GEMM_SMEM);
    cudaFuncSetAttribute(gemm_kernel<false,true ,false>, cudaFuncAttributeMaxDynamicSharedMemorySize, GEMM_SMEM);
    cudaFuncSetAttribute(gemm_kernel<true ,false,true >, cudaFuncAttributeMaxDynamicSharedMemorySize, GEMM_SMEM);

    // ---- weight + encoder conversions (per replay; deterministic) ----
    {
        int nW = WSEG;                       // 393216
        cvt_kernel<<<nW/1024, 256>>>(sa_Wq, hsaWq, nW);
        cvt_kernel<<<nW/1024, 256>>>(sa_Wk, hsaWk, nW);
        cvt_kernel<<<nW/1024, 256>>>(sa_Wv, hsaWv, nW);
        cvt_kernel<<<nW/1024, 256>>>(sa_Wo, hsaWo, nW);
        cvt_kernel<<<nW/1024, 256>>>(ca_Wq, hcaWq, nW);
        cvt_kernel<<<nW/1024, 256>>>(ca_Wk, hcaWk, nW);
        cvt_kernel<<<nW/1024, 256>>>(ca_Wv, hcaWv, nW);
        cvt_kernel<<<nW/1024, 256>>>(ca_Wo, hcaWo, nW);
        int nF = NLAYER*DMODEL*DFF;          // 1572864
        cvt_kernel<<<nF/1024, 256>>>(ff_W1, hffW1, nF);
        cvt_kernel<<<nF/1024, 256>>>(ff_W2, hffW2, nF);
        cvt_kernel<<<TD/1024, 256>>>(enc, ENCh, TD);
    }

    dim3 blkG(256), blkA(256), blkR(256);
    dim3 g_rows(TOK);
    dim3 g_qkv(12, 64);
    dim3 g_256(4, 64);
    dim3 g_1024(16, 64);
    dim3 g_attn(SEQ/64, NHEAD, BATCH);

    embed_kernel<<<g_rows, blkR>>>(dec, W_tgt, b_tgt, X, Xh);

    const int WD  = DMODEL*DMODEL;
    const int W1S = DMODEL*DFF;
    const int W2S = DFF*DMODEL;

    for (int i = 0; i < NLAYER; i++) {
        // ---- self attention ----
        {
            GArgs ga;
            ga.A[0]=Xh; ga.A[1]=Xh; ga.A[2]=Xh;
            ga.W[0]=hsaWq+i*WD; ga.W[1]=hsaWk+i*WD; ga.W[2]=hsaWv+i*WD;
            ga.bi[0]=sa_bq+i*DMODEL; ga.bi[1]=sa_bk+i*DMODEL; ga.bi[2]=sa_bv+i*DMODEL;
            ga.O[0]=Qh; ga.O[1]=Kh; ga.O[2]=Vh;
            gemm_kernel<false,false,true><<<g_qkv, blkG, GEMM_SMEM>>>(ga, nullptr, DMODEL, DMODEL, 2);
        }
        attn_kernel<<<g_attn, blkA, ATTN_SMEM>>>(Qh, Kh, Vh, Ch, dec_mask, SEQ, 1);
        {
            GArgs ga{};
            ga.A[0]=Ch; ga.W[0]=hsaWo+i*WD; ga.bi[0]=sa_bo+i*DMODEL; ga.O[0]=T;
            gemm_kernel<false,true,false><<<g_256, blkG, GEMM_SMEM>>>(ga, X, DMODEL, DMODEL, 2);
        }
        ln_kernel<<<g_rows, blkR>>>(T, sa_g+i*DMODEL, sa_b+i*DMODEL, X, Xh, 0);

        // ---- cross attention ----
        {
            GArgs ga;
            ga.A[0]=Xh; ga.A[1]=ENCh; ga.A[2]=ENCh;
            ga.W[0]=hcaWq+i*WD; ga.W[1]=hcaWk+i*WD; ga.W[2]=hcaWv+i*WD;
            ga.bi[0]=ca_bq+i*DMODEL; ga.bi[1]=ca_bk+i*DMODEL; ga.bi[2]=ca_bv+i*DMODEL;
            ga.O[0]=Qh; ga.O[1]=Kh; ga.O[2]=Vh;
            gemm_kernel<false,false,true><<<g_qkv, blkG, GEMM_SMEM>>>(ga, nullptr, DMODEL, DMODEL, 2);
        }
        attn_kernel<<<g_attn, blkA, ATTN_SMEM>>>(Qh, Kh, Vh, Ch, enc_mask, SEQ, 0);
        {
            GArgs ga{};
            ga.A[0]=Ch; ga.W[0]=hcaWo+i*WD; ga.bi[0]=ca_bo+i*DMODEL; ga.O[0]=T;
            gemm_kernel<false,true,false><<<g_256, blkG, GEMM_SMEM>>>(ga, X, DMODEL, DMODEL, 2);
        }
        ln_kernel<<<g_rows, blkR>>>(T, ca_g+i*DMODEL, ca_b+i*DMODEL, X, Xh, 0);

        // ---- FFN ----
        {
            GArgs ga{};
            ga.A[0]=Xh; ga.W[0]=hffW1+i*W1S; ga.bi[0]=ff_b1+i*DFF; ga.O[0]=Hh;
            gemm_kernel<true,false,true><<<g_1024, blkG, GEMM_SMEM>>>(ga, nullptr, DMODEL, DFF, 4);
        }
        {
            GArgs ga{};
            ga.A[0]=Hh; ga.W[0]=hffW2+i*W2S; ga.bi[0]=ff_b2+i*DMODEL; ga.O[0]=T;
            gemm_kernel<false,true,false><<<g_256, blkG, GEMM_SMEM>>>(ga, X, DFF, DMODEL, 2);
        }
        ln_kernel<<<g_rows, blkR>>>(T, ff_g+i*DMODEL, ff_b+i*DMODEL, X, Xh, (i < NLAYER-1) ? 1 : 0);
    }

    cudaMemcpyAsync(d_out, X, (size_t)TD*sizeof(float),
                    cudaMemcpyDeviceToDevice);
}